// round 7
// baseline (speedup 1.0000x reference)
#include <cuda_runtime.h>
#include <stdint.h>

// im:  [B=16, H=512, W=512, C=3] float32 in [0,1); it: [B,256,3] LUT
// out[b,h,w,c] = it[b, rn(255*im[b,h,w,c]), c]
//
// One-wave grid (1184 CTAs), float4 I/O, stcs stores.
// NEW: 8x bank-replicated smem LUT -> near-conflict-free random gather.
//   word address of (idx,c) for lane r-group: (3*idx+c)*8 + (lane & 7)
//   bank = (8k + r) % 32 == r (mod 8): disjoint bank sets per r-group.

#define B_DIM 16
#define PIX_PER_BATCH (512 * 512 * 3)        // 786432 floats
#define N4_PER_BATCH (PIX_PER_BATCH / 4)     // 196608 float4
#define LUT_FLOATS (256 * 3)                 // 768
#define REP 8
#define LUT_REP_FLOATS (LUT_FLOATS * REP)    // 6144 words = 24 KB
#define THREADS 256
#define BLOCKS_PER_BATCH 74                  // 1184 CTAs = one wave @ 8 CTA/SM
#define STRIDE (BLOCKS_PER_BATCH * THREADS)  // 18944

__device__ __forceinline__ int qidx(float v) {
    int i = __float2int_rn(255.0f * v);      // RNE, matches jnp.round on same product
    i = max(i, 0);
    i = min(i, 255);
    return i;
}

__device__ __forceinline__ float4 lookup4(const float* __restrict__ lutr,
                                          float4 v, int t) {
    // lutr is already offset by this thread's replica slot (lane & 7).
    // channel of component j of float4 t is (4t+j) % 3 == (t+j) % 3
    int c0 = t % 3;
    int c1 = c0 + 1; if (c1 == 3) c1 = 0;
    int c2 = c1 + 1; if (c2 == 3) c2 = 0;
    float4 r;
    r.x = lutr[(3 * qidx(v.x) + c0) * REP];
    r.y = lutr[(3 * qidx(v.y) + c1) * REP];
    r.z = lutr[(3 * qidx(v.z) + c2) * REP];
    r.w = lutr[(3 * qidx(v.w) + c0) * REP];
    return r;
}

__global__ void __launch_bounds__(THREADS)
intensity_transform_kernel(const float* __restrict__ im,
                           const float* __restrict__ it,
                           float* __restrict__ out) {
    __shared__ float lut[LUT_REP_FLOATS];    // lut[(3*idx+c)*8 + r]

    const int b = blockIdx.y;
    const float* __restrict__ itb = it + (size_t)b * LUT_FLOATS;

    // Fill replicated LUT: entry i -> 8 consecutive words, as two float4 stores.
    // 768 entries * 2 stores = 1536 float4 stores / 256 threads = 6 each.
    for (int i = threadIdx.x; i < LUT_FLOATS; i += THREADS) {
        float v = itb[i];
        float4 v4 = make_float4(v, v, v, v);
        float4* dst = reinterpret_cast<float4*>(&lut[i * REP]);
        dst[0] = v4;
        dst[1] = v4;
    }
    __syncthreads();

    const float* __restrict__ lutr = lut + (threadIdx.x & (REP - 1));

    const float4* __restrict__ in4 =
        reinterpret_cast<const float4*>(im + (size_t)b * PIX_PER_BATCH);
    float4* __restrict__ out4 =
        reinterpret_cast<float4*>(out + (size_t)b * PIX_PER_BATCH);

    int t = blockIdx.x * THREADS + threadIdx.x;

    #pragma unroll 2
    for (; t + STRIDE < N4_PER_BATCH; t += 2 * STRIDE) {
        float4 v0 = in4[t];
        float4 v1 = in4[t + STRIDE];
        float4 r0 = lookup4(lutr, v0, t);
        float4 r1 = lookup4(lutr, v1, t + STRIDE);
        __stcs(&out4[t], r0);
        __stcs(&out4[t + STRIDE], r1);
    }
    if (t < N4_PER_BATCH) {
        float4 v = in4[t];
        float4 r = lookup4(lutr, v, t);
        __stcs(&out4[t], r);
    }
}

extern "C" void kernel_launch(void* const* d_in, const int* in_sizes, int n_in,
                              void* d_out, int out_size) {
    const float* im = (const float*)d_in[0];
    const float* it = (const float*)d_in[1];
    float* out = (float*)d_out;

    dim3 grid(BLOCKS_PER_BATCH, B_DIM);
    intensity_transform_kernel<<<grid, THREADS>>>(im, it, out);
}